// round 10
// baseline (speedup 1.0000x reference)
#include <cuda_runtime.h>

#define N_WIRES 4
#define N_LAYERS 3
#define BATCH 65536
#define BN_EPS 1e-5f
#define PIX_F4 196               // 784 floats = 196 float4 per sample
#define INV196 (1.0f / 196.0f)
#define BLOCKS (BATCH / 64)      // 1024 blocks, 64 samples each (8 warps x 8 samples)
#define NORM_BLOCKS 256          // last 256 ticket-holders normalize
#define OUT_F4_PER_SHARD (BATCH / NORM_BLOCKS)   // 256 float4 per shard

// ---- device scratch (statically initialized data only; no allocations) ----
__device__ float g_part[BLOCKS * 8];     // per-block BN partials: 4 sums + 4 sumsqs
__device__ float g_scale[4];
__device__ float g_shift[4];
__device__ int g_counter = 0;            // completion tickets
__device__ volatile int g_ready = 0;     // stats-published flag
__device__ int g_done = 0;               // normalizer completion count

__device__ __forceinline__ float2 cmul(float2 a, float2 b) {
    return make_float2(a.x * b.x - a.y * b.y, a.x * b.y + a.y * b.x);
}
__device__ __forceinline__ float2 cadd(float2 a, float2 b) {
    return make_float2(a.x + b.x, a.y + b.y);
}

template <int D>
__device__ __forceinline__ void apply_gate(float2 s[16], float2 U00, float2 U01,
                                           float2 U10, float2 U11) {
#pragma unroll
    for (int i = 0; i < 16; ++i) {
        if (i & D) continue;
        float2 a = s[i];
        float2 b = s[i | D];
        s[i]     = cadd(cmul(U00, a), cmul(U01, b));
        s[i | D] = cadd(cmul(U10, a), cmul(U11, b));
    }
}

template <int C, int T>
__device__ __forceinline__ void cnot(float2 s[16]) {
#pragma unroll
    for (int i = 0; i < 16; ++i) {
        if (!(i & C) || (i & T)) continue;
        float2 t = s[i];
        s[i] = s[i | T];
        s[i | T] = t;
    }
}

template <int D>
__device__ __forceinline__ void do_wire(float2 st[16], const float2* M,
                                        float c, float s) {
    float2 M0 = M[0], M1 = M[1], M2 = M[2], M3 = M[3];
    float2 U00 = make_float2(M0.x * c + M1.x * s, M0.y * c + M1.y * s);
    float2 U01 = make_float2(M1.x * c - M0.x * s, M1.y * c - M0.y * s);
    float2 U10 = make_float2(M2.x * c + M3.x * s, M2.y * c + M3.y * s);
    float2 U11 = make_float2(M3.x * c - M2.x * s, M3.y * c - M2.y * s);
    apply_gate<D>(st, U00, U01, U10, U11);
}

// ================= single fused kernel =================
__global__ __launch_bounds__(256, 2) void fused_kernel(const float4* __restrict__ x4,
                                                       const float* __restrict__ params,
                                                       const float* __restrict__ W,
                                                       const float* __restrict__ b,
                                                       const float* __restrict__ bn_w,
                                                       const float* __restrict__ bn_b,
                                                       float4* __restrict__ out) {
    __shared__ float2 sM[N_LAYERS * N_WIRES][4];
    __shared__ float  sW[16], sb[4];
    __shared__ float  s_red[8][8];
    __shared__ float  s_acc[256];
    __shared__ int    s_ticket;

    const int tid = threadIdx.x;
    const int wrp = tid >> 5;
    const int lane = tid & 31;

    // --- per-block gate/linear precompute (redundant, trivial) ---
    if (tid < 12) {
        float t0 = params[tid * 3 + 0];
        float t1 = params[tid * 3 + 1];
        float s0, c0, s1, c1;
        sincosf(0.5f * t0, &s0, &c0);
        sincosf(0.5f * t1, &s1, &c1);
        sM[tid][0] = make_float2(c1 * c0, -c1 * s0);
        sM[tid][1] = make_float2(s1 * s0, -s1 * c0);
        sM[tid][2] = make_float2(-s1 * s0, -s1 * c0);
        sM[tid][3] = make_float2(c1 * c0, c1 * s0);
    }
    if (tid >= 16 && tid < 32) sW[tid - 16] = W[tid - 16];
    if (tid >= 32 && tid < 36) sb[tid - 32] = b[tid - 32];
    __syncthreads();

    // --- encode: warp streams its 8 samples (1568 float4, contiguous) ---
    const int wbase = (blockIdx.x * 8 + wrp) * 8;      // first sample of this warp
    const float4* __restrict__ p = x4 + (size_t)wbase * PIX_F4;

    float cur[32];                                      // partials per global chunk 0..31
#pragma unroll
    for (int g = 0; g < 32; ++g) cur[g] = 0.f;

#pragma unroll
    for (int k = 0; k < 49; ++k) {
        float4 f = __ldcs(p + 32 * k + lane);
        float s = (f.x + f.y) + (f.z + f.w);
        const int c0 = (32 * k) / 49;                   // compile-time after unroll
        const int B  = 49 * (c0 + 1) - 32 * k;          // boundary lane
        if (B >= 32)           cur[c0] += s;
        else if (lane < B)     cur[c0] += s;
        else                   cur[c0 + 1] += s;
    }

    // --- halving-exchange: 31 SHFLs reduce all 32 chunk sums; lane g gets chunk g ---
#pragma unroll
    for (int m = 16; m >= 1; m >>= 1) {
#pragma unroll
        for (int j = 0; j < m; ++j) {
            float send = (lane & m) ? cur[j] : cur[j + m];
            float recv = __shfl_xor_sync(0xffffffffu, send, m);
            float keep = (lane & m) ? cur[j + m] : cur[j];
            cur[j] = keep + recv;
        }
    }
    float tot = cur[0] * INV196;   // lane l: mean of chunk (l&3) of sample (l>>2)

    // gather my sample's 4 encoding angles (lanes 0-7 own samples; others duplicate)
    float e[4];
#pragma unroll
    for (int c = 0; c < 4; ++c)
        e[c] = __shfl_sync(0xffffffffu, tot, ((lane & 7) << 2) | c);

    // --- sim: one sample per lane (lanes 0-7 real) ---
    float cw[4], sw[4];
#pragma unroll
    for (int w = 0; w < 4; ++w) sincosf(0.5f * e[w], &sw[w], &cw[w]);

    float2 st[16];
#pragma unroll
    for (int i = 0; i < 16; ++i) st[i] = make_float2(0.f, 0.f);
    st[0] = make_float2(1.f, 0.f);

#pragma unroll
    for (int l = 0; l < N_LAYERS; ++l) {
        do_wire<1>(st, sM[l * 4 + 0], cw[0], sw[0]);
        cnot<1, 2>(st);
        do_wire<2>(st, sM[l * 4 + 1], cw[1], sw[1]);
        cnot<2, 4>(st);
        do_wire<4>(st, sM[l * 4 + 2], cw[2], sw[2]);
        cnot<4, 8>(st);
        do_wire<8>(st, sM[l * 4 + 3], cw[3], sw[3]);
    }

    float z[4] = {0.f, 0.f, 0.f, 0.f};
#pragma unroll
    for (int i = 0; i < 16; ++i) {
        float pr = st[i].x * st[i].x + st[i].y * st[i].y;
        z[0] += (i & 1) ? -pr : pr;
        z[1] += (i & 2) ? -pr : pr;
        z[2] += (i & 4) ? -pr : pr;
        z[3] += (i & 8) ? -pr : pr;
    }

    float o[4];
#pragma unroll
    for (int j = 0; j < 4; ++j) {
        float acc = sb[j];
#pragma unroll
        for (int w = 0; w < 4; ++w) acc += z[w] * sW[j * 4 + w];
        o[j] = acc;
    }

    if (lane < 8) out[wbase + lane] = make_float4(o[0], o[1], o[2], o[3]);
    else { o[0] = 0.f; o[1] = 0.f; o[2] = 0.f; o[3] = 0.f; }

    // --- BN partials: reduce over lanes 0-7 (others hold zeros) ---
    float red[8] = {o[0], o[1], o[2], o[3],
                    o[0] * o[0], o[1] * o[1], o[2] * o[2], o[3] * o[3]};
#pragma unroll
    for (int kk = 0; kk < 8; ++kk) {
        float v = red[kk];
        v += __shfl_xor_sync(0xffffffffu, v, 4);
        v += __shfl_xor_sync(0xffffffffu, v, 2);
        v += __shfl_xor_sync(0xffffffffu, v, 1);
        red[kk] = v;
    }
    if (lane == 0) {
#pragma unroll
        for (int kk = 0; kk < 8; ++kk) s_red[wrp][kk] = red[kk];
    }
    __syncthreads();
    if (tid < 8) {
        float v = 0.f;
#pragma unroll
        for (int w = 0; w < 8; ++w) v += s_red[w][tid];
        g_part[blockIdx.x * 8 + tid] = v;
    }

    // --- publish + ticket ---
    __threadfence();
    __syncthreads();
    if (tid == 0) s_ticket = atomicAdd(&g_counter, 1);
    __syncthreads();
    const int ticket = s_ticket;

    // --- last block: reduce partials, publish scale/shift ---
    if (ticket == BLOCKS - 1) {
        const int c = tid & 7, r = tid >> 3;
        float acc = 0.f;
#pragma unroll
        for (int rr = r; rr < BLOCKS; rr += 32)
            acc += __ldcg(&g_part[rr * 8 + c]);
        s_acc[tid] = acc;
        __syncthreads();
        if (tid < 8) {
            float v = 0.f;
#pragma unroll
            for (int k = 0; k < 32; ++k) v += s_acc[k * 8 + tid];
            s_acc[tid] = v;   // totals: 0-3 sums, 4-7 sumsqs
        }
        __syncthreads();
        if (tid < 4) {
            float mu  = s_acc[tid] * (1.0f / BATCH);
            float ex2 = s_acc[tid + 4] * (1.0f / BATCH);
            float var = ex2 - mu * mu;
            float sc = bn_w[tid] * rsqrtf(var + BN_EPS);
            g_scale[tid] = sc;
            g_shift[tid] = bn_b[tid] - mu * sc;
        }
        __threadfence();
        __syncthreads();
        if (tid == 0) g_ready = 1;
    }

    // --- last NORM_BLOCKS ticket-holders: normalize one shard each ---
    if (ticket >= BLOCKS - NORM_BLOCKS) {
        if (tid == 0) {
            while (g_ready == 0) { __nanosleep(100); }
        }
        __syncthreads();
        __threadfence();   // acquire: order subsequent reads after flag observation

        const float sc0 = __ldcg(&g_scale[0]), sc1 = __ldcg(&g_scale[1]);
        const float sc2 = __ldcg(&g_scale[2]), sc3 = __ldcg(&g_scale[3]);
        const float sh0 = __ldcg(&g_shift[0]), sh1 = __ldcg(&g_shift[1]);
        const float sh2 = __ldcg(&g_shift[2]), sh3 = __ldcg(&g_shift[3]);

        const int shard = ticket - (BLOCKS - NORM_BLOCKS);
        const int idx = shard * OUT_F4_PER_SHARD + tid;
        float4 v = __ldcg(&out[idx]);
        v.x = v.x * sc0 + sh0;
        v.y = v.y * sc1 + sh1;
        v.z = v.z * sc2 + sh2;
        v.w = v.w * sc3 + sh3;
        out[idx] = v;

        // reset state for next graph replay (last normalizer to finish)
        __threadfence();
        __syncthreads();
        if (tid == 0) {
            int d = atomicAdd(&g_done, 1);
            if (d == NORM_BLOCKS - 1) {
                g_counter = 0;
                g_done = 0;
                g_ready = 0;
            }
        }
    }
}

extern "C" void kernel_launch(void* const* d_in, const int* in_sizes, int n_in,
                              void* d_out, int out_size) {
    const float* x      = (const float*)d_in[0];
    const float* params = (const float*)d_in[1];
    const float* W      = (const float*)d_in[2];
    const float* b      = (const float*)d_in[3];
    const float* bn_w   = (const float*)d_in[4];
    const float* bn_b   = (const float*)d_in[5];
    float4* out = (float4*)d_out;

    fused_kernel<<<BLOCKS, 256>>>((const float4*)x, params, W, b, bn_w, bn_b, out);
}

// round 11
// speedup vs baseline: 1.1970x; 1.1970x over previous
#include <cuda_runtime.h>

#define N_WIRES 4
#define N_LAYERS 3
#define BATCH 65536
#define BN_EPS 1e-5f
#define PIX_F4 196               // 784 floats = 196 float4 per sample
#define INV196 (1.0f / 196.0f)
#define BLOCKS (BATCH / 64)      // 1024 blocks, 64 samples each (8 warps x 8 samples)
#define NORM_BLOCKS 256
#define OUT_F4_PER_SHARD (BATCH / NORM_BLOCKS)

// ---- device scratch (statically initialized; no allocations) ----
__device__ float g_part[BLOCKS * 8];
__device__ float g_scale[4];
__device__ float g_shift[4];
__device__ int g_counter = 0;
__device__ volatile int g_ready = 0;
__device__ int g_done = 0;

// ================= single fused kernel =================
__global__ __launch_bounds__(256, 3) void fused_kernel(const float4* __restrict__ x4,
                                                       const float* __restrict__ params,
                                                       const float* __restrict__ W,
                                                       const float* __restrict__ b,
                                                       const float* __restrict__ bn_w,
                                                       const float* __restrict__ bn_b,
                                                       float* __restrict__ outf) {
    __shared__ float2 sM[N_LAYERS * N_WIRES][4];
    __shared__ float  sW[16], sb[4];
    __shared__ float  s_red[8][8];
    __shared__ float  s_acc[256];
    __shared__ int    s_ticket;

    const int tid = threadIdx.x;
    const int wrp = tid >> 5;
    const int lane = tid & 31;
    const int q = lane & 3;          // amplitude group (b2,b3) AND wire index of my angle
    const unsigned FULL = 0xffffffffu;

    // --- per-block gate/linear precompute (redundant, trivial) ---
    if (tid < 12) {
        float t0 = params[tid * 3 + 0];
        float t1 = params[tid * 3 + 1];
        float s0, c0, s1, c1;
        sincosf(0.5f * t0, &s0, &c0);
        sincosf(0.5f * t1, &s1, &c1);
        sM[tid][0] = make_float2(c1 * c0, -c1 * s0);   // M00
        sM[tid][1] = make_float2(s1 * s0, -s1 * c0);   // M01
        sM[tid][2] = make_float2(-s1 * s0, -s1 * c0);  // M10
        sM[tid][3] = make_float2(c1 * c0, c1 * s0);    // M11
    }
    if (tid >= 16 && tid < 32) sW[tid - 16] = W[tid - 16];
    if (tid >= 32 && tid < 36) sb[tid - 32] = b[tid - 32];
    __syncthreads();

    // --- encode: warp streams its 8 samples (1568 contiguous float4) ---
    const int wbase = (blockIdx.x * 8 + wrp) * 8;
    const float4* __restrict__ p = x4 + (size_t)wbase * PIX_F4;

    float cur[32];
#pragma unroll
    for (int g = 0; g < 32; ++g) cur[g] = 0.f;

#pragma unroll
    for (int k = 0; k < 49; ++k) {
        float4 f = __ldcs(p + 32 * k + lane);
        float s = (f.x + f.y) + (f.z + f.w);
        const int c0 = (32 * k) / 49;
        const int B  = 49 * (c0 + 1) - 32 * k;
        if (B >= 32)           cur[c0] += s;
        else if (lane < B)     cur[c0] += s;
        else                   cur[c0 + 1] += s;
    }

    // halving-exchange: lane g ends with total of global chunk g (= wire g&3 of sample g>>2)
#pragma unroll
    for (int m = 16; m >= 1; m >>= 1) {
#pragma unroll
        for (int j = 0; j < m; ++j) {
            float send = (lane & m) ? cur[j] : cur[j + m];
            float recv = __shfl_xor_sync(FULL, send, m);
            float keep = (lane & m) ? cur[j + m] : cur[j];
            cur[j] = keep + recv;
        }
    }
    const float angle = cur[0] * INV196;   // my wire-q angle of my sample

    // --- distributed sim: 4 lanes per sample, lane q holds amplitudes (b2,b3)=q ---
    float c_own, s_own;
    sincosf(0.5f * angle, &s_own, &c_own);

    // broadcast all 4 wires' (cos, sin) within the 4-lane group
    const int gbase = lane & ~3;
    float cw[4], sw[4];
#pragma unroll
    for (int w = 0; w < 4; ++w) {
        cw[w] = __shfl_sync(FULL, c_own, gbase | w);
        sw[w] = __shfl_sync(FULL, s_own, gbase | w);
    }

    // my 4 amplitudes: index j = (b1<<1)|b0 ; global i = j | (q<<2)
    float ax[4] = {0.f, 0.f, 0.f, 0.f};
    float ay[4] = {0.f, 0.f, 0.f, 0.f};
    if (q == 0) ax[0] = 1.f;

    const bool pb2 = (q & 1) != 0;       // my b2
    const bool pb3 = (q & 2) != 0;       // my b3

#pragma unroll
    for (int l = 0; l < N_LAYERS; ++l) {
        // ===== wire 0: local pairs (0,1),(2,3), full U =====
        {
            float2 M0 = sM[l * 4 + 0][0], M1 = sM[l * 4 + 0][1];
            float2 M2 = sM[l * 4 + 0][2], M3 = sM[l * 4 + 0][3];
            float c = cw[0], s = sw[0];
            float u00x = M0.x * c + M1.x * s, u00y = M0.y * c + M1.y * s;
            float u01x = M1.x * c - M0.x * s, u01y = M1.y * c - M0.y * s;
            float u10x = M2.x * c + M3.x * s, u10y = M2.y * c + M3.y * s;
            float u11x = M3.x * c - M2.x * s, u11y = M3.y * c - M2.y * s;
#pragma unroll
            for (int pr = 0; pr < 2; ++pr) {
                int i0 = pr * 2, i1 = pr * 2 + 1;   // pairs (0,1),(2,3)
                float bx0 = ax[i0], by0 = ay[i0], bx1 = ax[i1], by1 = ay[i1];
                ax[i0] = u00x * bx0 - u00y * by0 + u01x * bx1 - u01y * by1;
                ay[i0] = u00x * by0 + u00y * bx0 + u01x * by1 + u01y * bx1;
                ax[i1] = u10x * bx0 - u10y * by0 + u11x * bx1 - u11y * by1;
                ay[i1] = u10x * by0 + u10y * bx0 + u11x * by1 + u11y * bx1;
            }
        }
        // CNOT(0,1): j with b0=1 flip b1 -> swap a[1]<->a[3]
        { float t; t = ax[1]; ax[1] = ax[3]; ax[3] = t; t = ay[1]; ay[1] = ay[3]; ay[3] = t; }

        // ===== wire 1: local pairs (0,2),(1,3), full U =====
        {
            float2 M0 = sM[l * 4 + 1][0], M1 = sM[l * 4 + 1][1];
            float2 M2 = sM[l * 4 + 1][2], M3 = sM[l * 4 + 1][3];
            float c = cw[1], s = sw[1];
            float u00x = M0.x * c + M1.x * s, u00y = M0.y * c + M1.y * s;
            float u01x = M1.x * c - M0.x * s, u01y = M1.y * c - M0.y * s;
            float u10x = M2.x * c + M3.x * s, u10y = M2.y * c + M3.y * s;
            float u11x = M3.x * c - M2.x * s, u11y = M3.y * c - M2.y * s;
#pragma unroll
            for (int pr = 0; pr < 2; ++pr) {
                int i0 = pr, i1 = pr + 2;           // pairs (0,2),(1,3)
                float bx0 = ax[i0], by0 = ay[i0], bx1 = ax[i1], by1 = ay[i1];
                ax[i0] = u00x * bx0 - u00y * by0 + u01x * bx1 - u01y * by1;
                ay[i0] = u00x * by0 + u00y * bx0 + u01x * by1 + u01y * bx1;
                ax[i1] = u10x * bx0 - u10y * by0 + u11x * bx1 - u11y * by1;
                ay[i1] = u10x * by0 + u10y * bx0 + u11x * by1 + u11y * bx1;
            }
        }
        // CNOT(1,2): j with b1=1 (j=2,3) exchange with lane q^1 (flip b2)
        ax[2] = __shfl_xor_sync(FULL, ax[2], 1); ay[2] = __shfl_xor_sync(FULL, ay[2], 1);
        ax[3] = __shfl_xor_sync(FULL, ax[3], 1); ay[3] = __shfl_xor_sync(FULL, ay[3], 1);

        // ===== wire 2 (b2): cross-lane q^1; row selected by my b2 =====
        {
            float2 M0 = sM[l * 4 + 2][0], M1 = sM[l * 4 + 2][1];
            float2 M2 = sM[l * 4 + 2][2], M3 = sM[l * 4 + 2][3];
            float c = cw[2], s = sw[2];
            float2 MA = pb2 ? M3 : M0;
            float2 MB = pb2 ? M2 : M1;
            float ss = pb2 ? -s : s;
            // Uown = MA*c + MB*ss ; Upart = MB*c - MA*ss
            float uox = MA.x * c + MB.x * ss, uoy = MA.y * c + MB.y * ss;
            float upx = MB.x * c - MA.x * ss, upy = MB.y * c - MA.y * ss;
#pragma unroll
            for (int j = 0; j < 4; ++j) {
                float px = __shfl_xor_sync(FULL, ax[j], 1);
                float py = __shfl_xor_sync(FULL, ay[j], 1);
                float nx = uox * ax[j] - uoy * ay[j] + upx * px - upy * py;
                float ny = uox * ay[j] + uoy * ax[j] + upx * py + upy * px;
                ax[j] = nx; ay[j] = ny;
            }
        }
        // CNOT(2,3): lanes with b2=1 exchange all amps with lane q^2 (flip b3)
#pragma unroll
        for (int j = 0; j < 4; ++j) {
            float tx = __shfl_xor_sync(FULL, ax[j], 2);
            float ty = __shfl_xor_sync(FULL, ay[j], 2);
            if (pb2) { ax[j] = tx; ay[j] = ty; }
        }

        // ===== wire 3 (b3): cross-lane q^2; row selected by my b3 =====
        {
            float2 M0 = sM[l * 4 + 3][0], M1 = sM[l * 4 + 3][1];
            float2 M2 = sM[l * 4 + 3][2], M3 = sM[l * 4 + 3][3];
            float c = cw[3], s = sw[3];
            float2 MA = pb3 ? M3 : M0;
            float2 MB = pb3 ? M2 : M1;
            float ss = pb3 ? -s : s;
            float uox = MA.x * c + MB.x * ss, uoy = MA.y * c + MB.y * ss;
            float upx = MB.x * c - MA.x * ss, upy = MB.y * c - MA.y * ss;
#pragma unroll
            for (int j = 0; j < 4; ++j) {
                float px = __shfl_xor_sync(FULL, ax[j], 2);
                float py = __shfl_xor_sync(FULL, ay[j], 2);
                float nx = uox * ax[j] - uoy * ay[j] + upx * px - upy * py;
                float ny = uox * ay[j] + uoy * ax[j] + upx * py + upy * px;
                ax[j] = nx; ay[j] = ny;
            }
        }
    }

    // --- PauliZ expvals ---
    float pj[4];
#pragma unroll
    for (int j = 0; j < 4; ++j) pj[j] = ax[j] * ax[j] + ay[j] * ay[j];
    float z0 = pj[0] - pj[1] + pj[2] - pj[3];        // sign by b0
    float z1 = pj[0] + pj[1] - pj[2] - pj[3];        // sign by b1
    float t  = pj[0] + pj[1] + pj[2] + pj[3];
    float z2 = pb2 ? -t : t;                          // sign by b2
    float z3 = pb3 ? -t : t;                          // sign by b3
#pragma unroll
    for (int m = 1; m <= 2; m <<= 1) {
        z0 += __shfl_xor_sync(FULL, z0, m);
        z1 += __shfl_xor_sync(FULL, z1, m);
        z2 += __shfl_xor_sync(FULL, z2, m);
        z3 += __shfl_xor_sync(FULL, z3, m);
    }

    // --- Linear: lane q computes output channel q of its sample ---
    float o = sb[q] + z0 * sW[q * 4 + 0] + z1 * sW[q * 4 + 1]
                    + z2 * sW[q * 4 + 2] + z3 * sW[q * 4 + 3];
    outf[wbase * 4 + lane] = o;   // 32 consecutive floats per warp

    // --- BN partials: sum channel q over the warp's 8 samples ---
    float v = o, vsq = o * o;
#pragma unroll
    for (int m = 4; m <= 16; m <<= 1) {
        v   += __shfl_xor_sync(FULL, v, m);
        vsq += __shfl_xor_sync(FULL, vsq, m);
    }
    if (lane < 4) { s_red[wrp][lane] = v; s_red[wrp][4 + lane] = vsq; }
    __syncthreads();
    if (tid < 8) {
        float acc = 0.f;
#pragma unroll
        for (int w = 0; w < 8; ++w) acc += s_red[w][tid];
        g_part[blockIdx.x * 8 + tid] = acc;
    }

    // --- publish + ticket ---
    __threadfence();
    __syncthreads();
    if (tid == 0) s_ticket = atomicAdd(&g_counter, 1);
    __syncthreads();
    const int ticket = s_ticket;

    // --- last block: reduce partials, publish scale/shift ---
    if (ticket == BLOCKS - 1) {
        const int c = tid & 7, r = tid >> 3;
        float acc = 0.f;
#pragma unroll
        for (int rr = r; rr < BLOCKS; rr += 32)
            acc += __ldcg(&g_part[rr * 8 + c]);
        s_acc[tid] = acc;
        __syncthreads();
        if (tid < 8) {
            float vv = 0.f;
#pragma unroll
            for (int k = 0; k < 32; ++k) vv += s_acc[k * 8 + tid];
            s_acc[tid] = vv;
        }
        __syncthreads();
        if (tid < 4) {
            float mu  = s_acc[tid] * (1.0f / BATCH);
            float ex2 = s_acc[tid + 4] * (1.0f / BATCH);
            float var = ex2 - mu * mu;
            float sc = bn_w[tid] * rsqrtf(var + BN_EPS);
            g_scale[tid] = sc;
            g_shift[tid] = bn_b[tid] - mu * sc;
        }
        __threadfence();
        __syncthreads();
        if (tid == 0) g_ready = 1;
    }

    // --- last NORM_BLOCKS ticket-holders: normalize one shard each ---
    if (ticket >= BLOCKS - NORM_BLOCKS) {
        if (tid == 0) {
            while (g_ready == 0) { __nanosleep(100); }
        }
        __syncthreads();
        __threadfence();

        const float sc0 = __ldcg(&g_scale[0]), sc1 = __ldcg(&g_scale[1]);
        const float sc2 = __ldcg(&g_scale[2]), sc3 = __ldcg(&g_scale[3]);
        const float sh0 = __ldcg(&g_shift[0]), sh1 = __ldcg(&g_shift[1]);
        const float sh2 = __ldcg(&g_shift[2]), sh3 = __ldcg(&g_shift[3]);

        const int shard = ticket - (BLOCKS - NORM_BLOCKS);
        const int idx = shard * OUT_F4_PER_SHARD + tid;
        float4* out4 = (float4*)outf;
        float4 vv = __ldcg(&out4[idx]);
        vv.x = vv.x * sc0 + sh0;
        vv.y = vv.y * sc1 + sh1;
        vv.z = vv.z * sc2 + sh2;
        vv.w = vv.w * sc3 + sh3;
        out4[idx] = vv;

        __threadfence();
        __syncthreads();
        if (tid == 0) {
            int d = atomicAdd(&g_done, 1);
            if (d == NORM_BLOCKS - 1) {
                g_counter = 0;
                g_done = 0;
                g_ready = 0;
            }
        }
    }
}

extern "C" void kernel_launch(void* const* d_in, const int* in_sizes, int n_in,
                              void* d_out, int out_size) {
    const float* x      = (const float*)d_in[0];
    const float* params = (const float*)d_in[1];
    const float* W      = (const float*)d_in[2];
    const float* b      = (const float*)d_in[3];
    const float* bn_w   = (const float*)d_in[4];
    const float* bn_b   = (const float*)d_in[5];

    fused_kernel<<<BLOCKS, 256>>>((const float4*)x, params, W, b, bn_w, bn_b,
                                  (float*)d_out);
}